// round 9
// baseline (speedup 1.0000x reference)
#include <cuda_runtime.h>
#include <math.h>
#include <stdint.h>

#define BHn   96
#define Nn    1024
#define Cc    64
#define RCc   32
#define RNn   128
#define NM1   1023
#define ROWS_TOT (BHn*NM1)   /* 98208 */
#define KTOP  16
#define BUDGET 256

typedef unsigned long long u64;
typedef unsigned u32;

// ---------------- scratch ----------------
__device__ __align__(16) float g_qp[BHn*Nn*RCc];
__device__ __align__(16) float g_kp[BHn*Nn*RCc];
__device__ __align__(16) float g_kp2p[8*BHn*RCc*RNn];
__device__ __align__(16) float g_kp2[BHn*RCc*RNn];
__device__ __align__(16) float g_basis[RNn*Nn];
__device__ __align__(16) u64   g_pair[(size_t)ROWS_TOT*KTOP];

// packed f32x2 helpers (bit-identical to scalar fma per component)
__device__ __forceinline__ void fma2(u64 &d, u64 a, u64 b) {
    asm("fma.rn.f32x2 %0, %1, %2, %0;" : "+l"(d) : "l"(a), "l"(b));
}
__device__ __forceinline__ u64 pk2(float x, float y) {
    u64 r; asm("mov.b64 %0, {%1, %2};" : "=l"(r) : "f"(x), "f"(y)); return r;
}
__device__ __forceinline__ void upk2(u64 v, float &x, float &y) {
    asm("mov.b64 {%0, %1}, %2;" : "=f"(x), "=f"(y) : "l"(v));
}

// ---------------- exact warp k-th largest (bit pattern), fixed-start (r8-measured) ----------------
template<int NW>
__device__ __forceinline__ u32 warp_kth_bits(const u64* w, int k, u32* sb, int lane) {
    const unsigned FULL = 0xffffffffu;
    unsigned pfx = 0u; int sh = 32;
    #pragma unroll 1
    for (int p = 0; p < 8; p++) {
        sh -= 4;
        u64 h0 = 0ULL, h1 = 0ULL;
        #pragma unroll
        for (int i = 0; i < NW; i++) {
            u64 a = w[i];
            #pragma unroll
            for (int hv = 0; hv < 2; hv++) {
                u32 u = (u32)(a >> (hv*32));
                bool match = (p == 0) || ((u >> (sh+4)) == (pfx >> (sh+4)));
                int bin = (u >> sh) & 15;
                u64 inc = 1ULL << ((bin & 7) << 3);
                if (match) { if (bin < 8) h0 += inc; else h1 += inc; }
            }
        }
        const u64 MB = 0x00FF00FF00FF00FFULL;
        u64 E0 = h0 & MB, O0 = (h0 >> 8) & MB;
        u64 E1 = h1 & MB, O1 = (h1 >> 8) & MB;
        u64 e0 = (u64)__reduce_add_sync(FULL,(u32)E0) | ((u64)__reduce_add_sync(FULL,(u32)(E0>>32)) << 32);
        u64 o0 = (u64)__reduce_add_sync(FULL,(u32)O0) | ((u64)__reduce_add_sync(FULL,(u32)(O0>>32)) << 32);
        u64 e1 = (u64)__reduce_add_sync(FULL,(u32)E1) | ((u64)__reduce_add_sync(FULL,(u32)(E1>>32)) << 32);
        u64 o1 = (u64)__reduce_add_sync(FULL,(u32)O1) | ((u64)__reduce_add_sync(FULL,(u32)(O1>>32)) << 32);
        int b = lane & 15;
        u64 srcw = (b < 8) ? ((b & 1) ? o0 : e0) : ((b & 1) ? o1 : e1);
        unsigned cntb = (unsigned)((srcw >> ((((b & 7) >> 1) & 3)*16)) & 0xFFFFu);
        unsigned S = cntb;
        #pragma unroll
        for (int off = 1; off <= 8; off <<= 1) {
            unsigned v = __shfl_down_sync(FULL, S, off);
            if (lane + off < 16) S += v;
        }
        bool hit = (lane < 16) && (S >= (unsigned)k) && (S - cntb < (unsigned)k);
        unsigned bal = __ballot_sync(FULL, hit);
        int bsel = __ffs(bal) - 1;
        unsigned S_s   = __shfl_sync(FULL, S,    bsel);
        unsigned cnt_s = __shfl_sync(FULL, cntb, bsel);
        pfx |= ((unsigned)bsel) << sh;
        k -= (int)(S_s - cnt_s);
        if (cnt_s <= 32 || sh == 0) break;
    }
    if (sh > 0) {
        unsigned cmpv = pfx >> sh;
        unsigned ltm = (1u << lane) - 1u;
        int base = 0;
        #pragma unroll
        for (int i = 0; i < NW; i++) {
            u64 a = w[i];
            #pragma unroll
            for (int hv = 0; hv < 2; hv++) {
                u32 u = (u32)(a >> (hv*32));
                bool f = (u >> sh) == cmpv;
                unsigned bal = __ballot_sync(FULL, f);
                if (f) sb[base + __popc(bal & ltm)] = u;
                base += __popc(bal);
            }
        }
        __syncwarp();
        bool valid = lane < base;
        u32 cand = sb[lane];
        unsigned thr = pfx;
        for (int bb = sh - 1; bb >= 0; bb--) {
            unsigned t2 = thr | (1u << bb);
            int cgt = __popc(__ballot_sync(FULL, valid && cand >= t2));
            if (cgt >= k) thr = t2;
        }
        pfx = thr;
        __syncwarp();
    }
    return pfx;
}

// ---------------- basis = Threshold(|proj_back_n.T|) ----------------
__global__ void k_basis(const float* __restrict__ pb) {
    int i = blockIdx.x*256 + threadIdx.x;
    if (i < RNn*Nn) {
        int j = i >> 7, c = i & 127;
        float v = fabsf(pb[i]);
        g_basis[(size_t)c*Nn + j] = (v > 0.02f) ? v : 0.0f;
    }
}

// ---------------- qp / kp projection ----------------
__global__ void k_proj(const float* __restrict__ x, const float* __restrict__ w,
                       const float* __restrict__ b, int which) {
    float* out = which ? g_kp : g_qp;
    int warp = threadIdx.x >> 5, lane = threadIdx.x & 31;
    int row0 = (blockIdx.x*8 + warp)*16;
    float wr[64];
    #pragma unroll
    for (int c4 = 0; c4 < 16; c4++) {
        float4 t = *(const float4*)(w + lane*64 + c4*4);
        wr[c4*4+0]=t.x; wr[c4*4+1]=t.y; wr[c4*4+2]=t.z; wr[c4*4+3]=t.w;
    }
    float bias = b[lane];
    for (int r = 0; r < 16; r++) {
        int row = row0 + r;
        float qlo = x[(size_t)row*64 + lane];
        float qhi = x[(size_t)row*64 + 32 + lane];
        float acc = 0.0f;
        #pragma unroll
        for (int c = 0; c < 32; c++) acc = fmaf(__shfl_sync(0xffffffffu, qlo, c), wr[c],    acc);
        #pragma unroll
        for (int c = 0; c < 32; c++) acc = fmaf(__shfl_sync(0xffffffffu, qhi, c), wr[32+c], acc);
        out[(size_t)row*32 + lane] = acc + bias;
    }
}

// ---------------- kp2 partial ----------------
__global__ __launch_bounds__(256) void k_kp2_part(const float* __restrict__ proj_n) {
    __shared__ float kp_s[128*32];
    __shared__ float pj_s[128*64];
    int bh = blockIdx.x, ch = blockIdx.y, half = blockIdx.z;
    int n0 = ch*128, rnb = half*64, tid = threadIdx.x;
    const float4* src = (const float4*)(g_kp + ((size_t)bh*Nn + n0)*32);
    for (int i = tid; i < 1024; i += 256) ((float4*)kp_s)[i] = src[i];
    for (int i = tid; i < 2048; i += 256) {
        int r = i >> 4, c4 = i & 15;
        ((float4*)pj_s)[i] = *((const float4*)(proj_n + (size_t)(n0+r)*128 + rnb) + c4);
    }
    __syncthreads();
    int rc0 = (tid & 7)*4;
    int rn0 = (tid >> 3)*2;
    float a00=0,a01=0,a10=0,a11=0,a20=0,a21=0,a30=0,a31=0;
    #pragma unroll 4
    for (int n = 0; n < 128; n++) {
        float4 a = *(const float4*)(kp_s + n*32 + rc0);
        float2 p = *(const float2*)(pj_s + n*64 + rn0);
        a00 = fmaf(a.x, p.x, a00); a01 = fmaf(a.x, p.y, a01);
        a10 = fmaf(a.y, p.x, a10); a11 = fmaf(a.y, p.y, a11);
        a20 = fmaf(a.z, p.x, a20); a21 = fmaf(a.z, p.y, a21);
        a30 = fmaf(a.w, p.x, a30); a31 = fmaf(a.w, p.y, a31);
    }
    float* outp = g_kp2p + ((size_t)ch*BHn + bh)*4096 + rnb + rn0;
    *(float2*)(outp + (rc0+0)*128) = make_float2(a00, a01);
    *(float2*)(outp + (rc0+1)*128) = make_float2(a10, a11);
    *(float2*)(outp + (rc0+2)*128) = make_float2(a20, a21);
    *(float2*)(outp + (rc0+3)*128) = make_float2(a30, a31);
}

__global__ void k_kp2_red() {
    int i = blockIdx.x*256 + threadIdx.x;
    if (i < BHn*RCc*RNn) {
        float s = 0.0f;
        #pragma unroll
        for (int ch = 0; ch < 8; ch++) s += g_kp2p[(size_t)ch*BHn*4096 + i];
        g_kp2[i] = s;
    }
}

// ---------------- phase A: cheap_attn + softmax + radix topk16 -> coef + g_pair ----------------
__global__ __launch_bounds__(128) void k_cheap(float* __restrict__ out_coef) {
    __shared__ u32 sm_cand[4][32];
    int warp = threadIdx.x >> 5, lane = threadIdx.x & 31;
    const unsigned FULL = 0xffffffffu;
    int rr = blockIdx.x*4 + warp;
    int bh = rr / NM1;
    int n  = rr - bh*NM1 + 1;

    float qv = g_qp[((size_t)bh*Nn + n)*32 + lane];
    const float4* kb = (const float4*)(g_kp2 + (size_t)bh*4096);
    float4 accq = {0.f,0.f,0.f,0.f};
    #pragma unroll
    for (int rc = 0; rc < 32; rc++) {
        float a = __shfl_sync(FULL, qv, rc);
        float4 kv = __ldg(kb + rc*32 + lane);
        accq.x = fmaf(a, kv.x, accq.x);
        accq.y = fmaf(a, kv.y, accq.y);
        accq.z = fmaf(a, kv.z, accq.z);
        accq.w = fmaf(a, kv.w, accq.w);
    }
    const float scale = 0.28867513459481287f;
    float l[4] = {accq.x*scale, accq.y*scale, accq.z*scale, accq.w*scale};
    float m = fmaxf(fmaxf(l[0], l[1]), fmaxf(l[2], l[3]));
    #pragma unroll
    for (int off = 16; off; off >>= 1) m = fmaxf(m, __shfl_xor_sync(FULL, m, off));
    float e[4], s = 0.0f;
    #pragma unroll
    for (int j = 0; j < 4; j++) { e[j] = expf(l[j] - m); s += e[j]; }
    #pragma unroll
    for (int off = 16; off; off >>= 1) s += __shfl_xor_sync(FULL, s, off);
    float c[4];
    #pragma unroll
    for (int j = 0; j < 4; j++) c[j] = e[j] / s;

    u32 vb[4];
    #pragma unroll
    for (int j = 0; j < 4; j++) vb[j] = __float_as_uint(c[j]);
    u64 w16[2] = { (u64)vb[0] | ((u64)vb[1] << 32), (u64)vb[2] | ((u64)vb[3] << 32) };
    u32 T = warp_kth_bits<2>(w16, KTOP, sm_cand[warp], lane);

    bool gt[4], eq[4];
    #pragma unroll
    for (int j = 0; j < 4; j++) { gt[j] = vb[j] > T; eq[j] = vb[j] == T; }
    unsigned balg0 = __ballot_sync(FULL, gt[0]), balg1 = __ballot_sync(FULL, gt[1]);
    unsigned balg2 = __ballot_sync(FULL, gt[2]), balg3 = __ballot_sync(FULL, gt[3]);
    unsigned bale0 = __ballot_sync(FULL, eq[0]), bale1 = __ballot_sync(FULL, eq[1]);
    unsigned bale2 = __ballot_sync(FULL, eq[2]), bale3 = __ballot_sync(FULL, eq[3]);
    int mgt = __popc(balg0) + __popc(balg1) + __popc(balg2) + __popc(balg3);
    int need = KTOP - mgt;
    unsigned ltm = (1u << lane) - 1u;
    int eq_before = __popc(bale0 & ltm) + __popc(bale1 & ltm) + __popc(bale2 & ltm) + __popc(bale3 & ltm);
    bool sel[4];
    int eqrun = eq_before;
    #pragma unroll
    for (int j = 0; j < 4; j++) {
        sel[j] = gt[j] || (eq[j] && (eqrun < need));
        if (eq[j]) eqrun++;
    }

    {
        float4 o;
        o.x = sel[0] ? c[0] : 0.0f;
        o.y = sel[1] ? c[1] : 0.0f;
        o.z = sel[2] ? c[2] : 0.0f;
        o.w = sel[3] ? c[3] : 0.0f;
        __stcs((float4*)(out_coef + (size_t)rr*128) + lane, o);
    }

    unsigned bs0 = __ballot_sync(FULL, sel[0]), bs1 = __ballot_sync(FULL, sel[1]);
    unsigned bs2 = __ballot_sync(FULL, sel[2]), bs3 = __ballot_sync(FULL, sel[3]);
    int run = __popc(bs0 & ltm) + __popc(bs1 & ltm) + __popc(bs2 & ltm) + __popc(bs3 & ltm);
    #pragma unroll
    for (int j = 0; j < 4; j++) {
        if (sel[j]) { g_pair[(size_t)rr*16 + run] = ((u64)(unsigned)(lane*4 + j) << 32) | (u64)vb[j]; run++; }
    }
}

// ---------------- phase B: column-chunked SpMM, basis chunk in smem ----------------
extern __shared__ float sm_bs[];
__global__ __launch_bounds__(256) void k_spmm(float* __restrict__ out_approx) {
    const unsigned FULL = 0xffffffffu;
    int ch = blockIdx.y;
    float4* bs4 = (float4*)sm_bs;                  // [128 rows][32 float4]
    const float4* gb = (const float4*)g_basis;
    for (int i = threadIdx.x; i < 4096; i += 256) {
        int r = i >> 5, c = i & 31;
        bs4[i] = gb[(size_t)r*256 + ch*32 + c];
    }
    __syncthreads();
    int warp = threadIdx.x >> 5, lane = threadIdx.x & 31;
    int row0 = blockIdx.x*256 + warp*32;
    #pragma unroll 1
    for (int it = 0; it < 32; it++) {
        int rr = row0 + it;
        if (rr >= ROWS_TOT) break;
        u64 mypr = (lane < 16) ? __ldg(g_pair + (size_t)rr*16 + lane) : 0ULL;
        u64 a0 = 0ULL, a1 = 0ULL;
        #pragma unroll
        for (int t = 0; t < 16; t++) {
            u64 pr = __shfl_sync(FULL, mypr, t);
            int   ci = (int)(pr >> 32);
            float v  = __uint_as_float((u32)pr);
            u64 vv = pk2(v, v);
            float4 x = bs4[ci*32 + lane];
            fma2(a0, pk2(x.x, x.y), vv);
            fma2(a1, pk2(x.z, x.w), vv);
        }
        float4 o;
        upk2(a0, o.x, o.y);
        upk2(a1, o.z, o.w);
        __stcs((float4*)(out_approx + (size_t)rr*1024) + ch*32 + lane, o);
    }
}

// ---------------- phase C: read approx, exact top-256, write mask (+cls) ----------------
__global__ __launch_bounds__(128) void k_mask(const float* __restrict__ approx,
                                              float* __restrict__ out_mask) {
    __shared__ u32 sm_cand[4][32];
    int warp = threadIdx.x >> 5, lane = threadIdx.x & 31;
    int rr = blockIdx.x*4 + warp;
    int bh = rr / NM1;
    int n  = rr - bh*NM1 + 1;

    u64 acc[16];
    const float4* rp = (const float4*)(approx + (size_t)rr*1024);
    #pragma unroll
    for (int j = 0; j < 8; j++) {
        float4 x = __ldcs(rp + j*32 + lane);
        acc[2*j]   = pk2(x.x, x.y);
        acc[2*j+1] = pk2(x.z, x.w);
    }

    u32 prefix = warp_kth_bits<16>(acc, BUDGET, sm_cand[warp], lane);

    float* mout = out_mask + ((size_t)bh*Nn + n)*Nn;
    #pragma unroll
    for (int j = 0; j < 8; j++) {
        unsigned u0 = (unsigned)(acc[2*j]);
        unsigned u1 = (unsigned)(acc[2*j] >> 32);
        unsigned u2 = (unsigned)(acc[2*j+1]);
        unsigned u3 = (unsigned)(acc[2*j+1] >> 32);
        float4 mo;
        mo.x = (u0 >= prefix) ? 1.0f : 0.0f;
        mo.y = (u1 >= prefix) ? 1.0f : 0.0f;
        mo.z = (u2 >= prefix) ? 1.0f : 0.0f;
        mo.w = (u3 >= prefix) ? 1.0f : 0.0f;
        __stcs((float4*)mout + j*32 + lane, mo);
    }

    if (n == 1) {
        float* cout = out_mask + (size_t)bh*Nn*Nn;
        float4 one4 = {1.0f, 1.0f, 1.0f, 1.0f};
        #pragma unroll
        for (int j = 0; j < 8; j++)
            __stcs((float4*)cout + j*32 + lane, one4);
    }
}

// ---------------- launch ----------------
extern "C" void kernel_launch(void* const* d_in, const int* in_sizes, int n_in,
                              void* d_out, int out_size) {
    const float* q  = (const float*)d_in[0];
    const float* k  = (const float*)d_in[1];
    const float* wq = (const float*)d_in[2];
    const float* bq = (const float*)d_in[3];
    const float* wk = (const float*)d_in[4];
    const float* bk = (const float*)d_in[5];
    const float* pn = (const float*)d_in[6];
    const float* pb = (const float*)d_in[7];

    float* out        = (float*)d_out;
    float* out_coef   = out;
    float* out_approx = out + (size_t)ROWS_TOT*RNn;
    float* out_mask   = out_approx + (size_t)ROWS_TOT*Nn;

    cudaFuncSetAttribute(k_spmm, cudaFuncAttributeMaxDynamicSharedMemorySize, 65536);

    k_basis<<<512, 256>>>(pb);
    k_proj<<<768, 256>>>(q, wq, bq, 0);
    k_proj<<<768, 256>>>(k, wk, bk, 1);
    k_kp2_part<<<dim3(BHn, 8, 2), 256>>>(pn);
    k_kp2_red<<<1536, 256>>>();
    k_cheap<<<ROWS_TOT/4, 128>>>(out_coef);
    k_spmm<<<dim3((ROWS_TOT + 255)/256, 8), 256, 65536>>>(out_approx);
    k_mask<<<ROWS_TOT/4, 128>>>(out_approx, out_mask);
}

// round 12
// speedup vs baseline: 2.1073x; 2.1073x over previous
#include <cuda_runtime.h>
#include <math.h>
#include <stdint.h>

#define BHn   96
#define Nn    1024
#define Cc    64
#define RCc   32
#define RNn   128
#define NM1   1023
#define ROWS_TOT (BHn*NM1)   /* 98208 */
#define KTOP  16
#define BUDGET 256

typedef unsigned long long u64;
typedef unsigned u32;

// ---------------- scratch ----------------
__device__ __align__(16) float g_qp[BHn*Nn*RCc];
__device__ __align__(16) float g_kp[BHn*Nn*RCc];
__device__ __align__(16) float g_kp2p[8*BHn*RCc*RNn];
__device__ __align__(16) float g_kp2[BHn*RCc*RNn];
__device__ __align__(16) float g_basis[RNn*Nn];

// packed f32x2 helpers (bit-identical to scalar fma per component)
__device__ __forceinline__ void fma2(u64 &d, u64 a, u64 b) {
    asm("fma.rn.f32x2 %0, %1, %2, %0;" : "+l"(d) : "l"(a), "l"(b));
}
__device__ __forceinline__ u64 pk2(float x, float y) {
    u64 r; asm("mov.b64 %0, {%1, %2};" : "=l"(r) : "f"(x), "f"(y)); return r;
}
__device__ __forceinline__ void upk2(u64 v, float &x, float &y) {
    asm("mov.b64 {%0, %1}, %2;" : "=f"(x), "=f"(y) : "l"(v));
}

// ---------------- exact warp k-th largest (bit pattern), fixed-start (r8-measured) ----------------
template<int NW>
__device__ __forceinline__ u32 warp_kth_bits(const u64* w, int k, u32* sb, int lane) {
    const unsigned FULL = 0xffffffffu;
    unsigned pfx = 0u; int sh = 32;
    #pragma unroll 1
    for (int p = 0; p < 8; p++) {
        sh -= 4;
        u64 h0 = 0ULL, h1 = 0ULL;
        #pragma unroll
        for (int i = 0; i < NW; i++) {
            u64 a = w[i];
            #pragma unroll
            for (int hv = 0; hv < 2; hv++) {
                u32 u = (u32)(a >> (hv*32));
                bool match = (p == 0) || ((u >> (sh+4)) == (pfx >> (sh+4)));
                int bin = (u >> sh) & 15;
                u64 inc = 1ULL << ((bin & 7) << 3);
                if (match) { if (bin < 8) h0 += inc; else h1 += inc; }
            }
        }
        const u64 MB = 0x00FF00FF00FF00FFULL;
        u64 E0 = h0 & MB, O0 = (h0 >> 8) & MB;
        u64 E1 = h1 & MB, O1 = (h1 >> 8) & MB;
        u64 e0 = (u64)__reduce_add_sync(FULL,(u32)E0) | ((u64)__reduce_add_sync(FULL,(u32)(E0>>32)) << 32);
        u64 o0 = (u64)__reduce_add_sync(FULL,(u32)O0) | ((u64)__reduce_add_sync(FULL,(u32)(O0>>32)) << 32);
        u64 e1 = (u64)__reduce_add_sync(FULL,(u32)E1) | ((u64)__reduce_add_sync(FULL,(u32)(E1>>32)) << 32);
        u64 o1 = (u64)__reduce_add_sync(FULL,(u32)O1) | ((u64)__reduce_add_sync(FULL,(u32)(O1>>32)) << 32);
        int b = lane & 15;
        u64 srcw = (b < 8) ? ((b & 1) ? o0 : e0) : ((b & 1) ? o1 : e1);
        unsigned cntb = (unsigned)((srcw >> ((((b & 7) >> 1) & 3)*16)) & 0xFFFFu);
        unsigned S = cntb;
        #pragma unroll
        for (int off = 1; off <= 8; off <<= 1) {
            unsigned v = __shfl_down_sync(FULL, S, off);
            if (lane + off < 16) S += v;
        }
        bool hit = (lane < 16) && (S >= (unsigned)k) && (S - cntb < (unsigned)k);
        unsigned bal = __ballot_sync(FULL, hit);
        int bsel = __ffs(bal) - 1;
        unsigned S_s   = __shfl_sync(FULL, S,    bsel);
        unsigned cnt_s = __shfl_sync(FULL, cntb, bsel);
        pfx |= ((unsigned)bsel) << sh;
        k -= (int)(S_s - cnt_s);
        if (cnt_s <= 32 || sh == 0) break;
    }
    if (sh > 0) {
        unsigned cmpv = pfx >> sh;
        unsigned ltm = (1u << lane) - 1u;
        int base = 0;
        #pragma unroll
        for (int i = 0; i < NW; i++) {
            u64 a = w[i];
            #pragma unroll
            for (int hv = 0; hv < 2; hv++) {
                u32 u = (u32)(a >> (hv*32));
                bool f = (u >> sh) == cmpv;
                unsigned bal = __ballot_sync(FULL, f);
                if (f) sb[base + __popc(bal & ltm)] = u;
                base += __popc(bal);
            }
        }
        __syncwarp();
        bool valid = lane < base;
        u32 cand = sb[lane];
        unsigned thr = pfx;
        for (int bb = sh - 1; bb >= 0; bb--) {
            unsigned t2 = thr | (1u << bb);
            int cgt = __popc(__ballot_sync(FULL, valid && cand >= t2));
            if (cgt >= k) thr = t2;
        }
        pfx = thr;
        __syncwarp();
    }
    return pfx;
}

// ---------------- fused prep: basis threshold + q projection + k projection ----------------
// blocks [0,512): basis; [512,1280): q proj; [1280,2048): k proj.
__global__ __launch_bounds__(256) void k_prep(const float* __restrict__ q,
                                              const float* __restrict__ kin,
                                              const float* __restrict__ wq,
                                              const float* __restrict__ bq,
                                              const float* __restrict__ wk,
                                              const float* __restrict__ bk,
                                              const float* __restrict__ pb) {
    int bid = blockIdx.x;
    if (bid < 512) {
        int i = bid*256 + threadIdx.x;
        if (i < RNn*Nn) {
            int j = i >> 7, c = i & 127;
            float v = fabsf(pb[i]);
            g_basis[(size_t)c*Nn + j] = (v > 0.02f) ? v : 0.0f;
        }
        return;
    }
    const float* x;
    const float* w;
    const float* b;
    float* out;
    int pbid;
    if (bid < 1280) { x = q;   w = wq; b = bq; out = g_qp; pbid = bid - 512; }
    else            { x = kin; w = wk; b = bk; out = g_kp; pbid = bid - 1280; }

    int warp = threadIdx.x >> 5, lane = threadIdx.x & 31;
    int row0 = (pbid*8 + warp)*16;
    float wr[64];
    #pragma unroll
    for (int c4 = 0; c4 < 16; c4++) {
        float4 t = *(const float4*)(w + lane*64 + c4*4);
        wr[c4*4+0]=t.x; wr[c4*4+1]=t.y; wr[c4*4+2]=t.z; wr[c4*4+3]=t.w;
    }
    float bias = b[lane];
    for (int r = 0; r < 16; r++) {
        int row = row0 + r;
        float qlo = x[(size_t)row*64 + lane];
        float qhi = x[(size_t)row*64 + 32 + lane];
        float acc = 0.0f;
        #pragma unroll
        for (int c = 0; c < 32; c++) acc = fmaf(__shfl_sync(0xffffffffu, qlo, c), wr[c],    acc);
        #pragma unroll
        for (int c = 0; c < 32; c++) acc = fmaf(__shfl_sync(0xffffffffu, qhi, c), wr[32+c], acc);
        out[(size_t)row*32 + lane] = acc + bias;
    }
}

// ---------------- kp2 partial ----------------
__global__ __launch_bounds__(256) void k_kp2_part(const float* __restrict__ proj_n) {
    __shared__ float kp_s[128*32];
    __shared__ float pj_s[128*64];
    int bh = blockIdx.x, ch = blockIdx.y, half = blockIdx.z;
    int n0 = ch*128, rnb = half*64, tid = threadIdx.x;
    const float4* src = (const float4*)(g_kp + ((size_t)bh*Nn + n0)*32);
    for (int i = tid; i < 1024; i += 256) ((float4*)kp_s)[i] = src[i];
    for (int i = tid; i < 2048; i += 256) {
        int r = i >> 4, c4 = i & 15;
        ((float4*)pj_s)[i] = *((const float4*)(proj_n + (size_t)(n0+r)*128 + rnb) + c4);
    }
    __syncthreads();
    int rc0 = (tid & 7)*4;
    int rn0 = (tid >> 3)*2;
    float a00=0,a01=0,a10=0,a11=0,a20=0,a21=0,a30=0,a31=0;
    #pragma unroll 4
    for (int n = 0; n < 128; n++) {
        float4 a = *(const float4*)(kp_s + n*32 + rc0);
        float2 p = *(const float2*)(pj_s + n*64 + rn0);
        a00 = fmaf(a.x, p.x, a00); a01 = fmaf(a.x, p.y, a01);
        a10 = fmaf(a.y, p.x, a10); a11 = fmaf(a.y, p.y, a11);
        a20 = fmaf(a.z, p.x, a20); a21 = fmaf(a.z, p.y, a21);
        a30 = fmaf(a.w, p.x, a30); a31 = fmaf(a.w, p.y, a31);
    }
    float* outp = g_kp2p + ((size_t)ch*BHn + bh)*4096 + rnb + rn0;
    *(float2*)(outp + (rc0+0)*128) = make_float2(a00, a01);
    *(float2*)(outp + (rc0+1)*128) = make_float2(a10, a11);
    *(float2*)(outp + (rc0+2)*128) = make_float2(a20, a21);
    *(float2*)(outp + (rc0+3)*128) = make_float2(a30, a31);
}

__global__ void k_kp2_red() {
    int i = blockIdx.x*256 + threadIdx.x;
    if (i < BHn*RCc*RNn) {
        float s = 0.0f;
        #pragma unroll
        for (int ch = 0; ch < 8; ch++) s += g_kp2p[(size_t)ch*BHn*4096 + i];
        g_kp2[i] = s;
    }
}

// ---------------- fused main (byte-identical to r8): cheap+softmax+topk16+SpMM+top256+cls ----------------
__global__ __launch_bounds__(128) void k_main(float* __restrict__ out_coef,
                                              float* __restrict__ out_approx,
                                              float* __restrict__ out_mask) {
    __shared__ u64 sm_pair[4][16];
    __shared__ u32 sm_cand[4][32];
    int warp = threadIdx.x >> 5, lane = threadIdx.x & 31;
    const unsigned FULL = 0xffffffffu;
    int rr = blockIdx.x*4 + warp;
    int bh = rr / NM1;
    int n  = rr - bh*NM1 + 1;

    float qv = g_qp[((size_t)bh*Nn + n)*32 + lane];
    const float4* kb = (const float4*)(g_kp2 + (size_t)bh*4096);
    float4 accq = {0.f,0.f,0.f,0.f};
    #pragma unroll
    for (int rc = 0; rc < 32; rc++) {
        float a = __shfl_sync(FULL, qv, rc);
        float4 kv = __ldg(kb + rc*32 + lane);
        accq.x = fmaf(a, kv.x, accq.x);
        accq.y = fmaf(a, kv.y, accq.y);
        accq.z = fmaf(a, kv.z, accq.z);
        accq.w = fmaf(a, kv.w, accq.w);
    }
    const float scale = 0.28867513459481287f;
    float l[4] = {accq.x*scale, accq.y*scale, accq.z*scale, accq.w*scale};
    float m = fmaxf(fmaxf(l[0], l[1]), fmaxf(l[2], l[3]));
    #pragma unroll
    for (int off = 16; off; off >>= 1) m = fmaxf(m, __shfl_xor_sync(FULL, m, off));
    float e[4], s = 0.0f;
    #pragma unroll
    for (int j = 0; j < 4; j++) { e[j] = expf(l[j] - m); s += e[j]; }
    #pragma unroll
    for (int off = 16; off; off >>= 1) s += __shfl_xor_sync(FULL, s, off);
    float c[4];
    #pragma unroll
    for (int j = 0; j < 4; j++) c[j] = e[j] / s;

    u32 vb[4];
    #pragma unroll
    for (int j = 0; j < 4; j++) vb[j] = __float_as_uint(c[j]);
    u64 w16[2] = { (u64)vb[0] | ((u64)vb[1] << 32), (u64)vb[2] | ((u64)vb[3] << 32) };
    u32 T = warp_kth_bits<2>(w16, KTOP, sm_cand[warp], lane);

    bool gt[4], eq[4];
    #pragma unroll
    for (int j = 0; j < 4; j++) { gt[j] = vb[j] > T; eq[j] = vb[j] == T; }
    unsigned balg0 = __ballot_sync(FULL, gt[0]), balg1 = __ballot_sync(FULL, gt[1]);
    unsigned balg2 = __ballot_sync(FULL, gt[2]), balg3 = __ballot_sync(FULL, gt[3]);
    unsigned bale0 = __ballot_sync(FULL, eq[0]), bale1 = __ballot_sync(FULL, eq[1]);
    unsigned bale2 = __ballot_sync(FULL, eq[2]), bale3 = __ballot_sync(FULL, eq[3]);
    int mgt = __popc(balg0) + __popc(balg1) + __popc(balg2) + __popc(balg3);
    int need = KTOP - mgt;
    unsigned ltm = (1u << lane) - 1u;
    int eq_before = __popc(bale0 & ltm) + __popc(bale1 & ltm) + __popc(bale2 & ltm) + __popc(bale3 & ltm);
    bool sel[4];
    int eqrun = eq_before;
    #pragma unroll
    for (int j = 0; j < 4; j++) {
        sel[j] = gt[j] || (eq[j] && (eqrun < need));
        if (eq[j]) eqrun++;
    }

    {
        float4 o;
        o.x = sel[0] ? c[0] : 0.0f;
        o.y = sel[1] ? c[1] : 0.0f;
        o.z = sel[2] ? c[2] : 0.0f;
        o.w = sel[3] ? c[3] : 0.0f;
        *(float4*)(out_coef + (size_t)rr*128 + lane*4) = o;
    }

    unsigned bs0 = __ballot_sync(FULL, sel[0]), bs1 = __ballot_sync(FULL, sel[1]);
    unsigned bs2 = __ballot_sync(FULL, sel[2]), bs3 = __ballot_sync(FULL, sel[3]);
    int run = __popc(bs0 & ltm) + __popc(bs1 & ltm) + __popc(bs2 & ltm) + __popc(bs3 & ltm);
    #pragma unroll
    for (int j = 0; j < 4; j++) {
        if (sel[j]) { sm_pair[warp][run] = ((u64)(unsigned)(lane*4 + j) << 32) | (u64)vb[j]; run++; }
    }
    __syncwarp();

    u64 acc[16];
    #pragma unroll
    for (int j = 0; j < 16; j++) acc[j] = 0ULL;
    #pragma unroll 4
    for (int t = 0; t < 16; t++) {
        u64 pr = sm_pair[warp][t];
        int   ci = (int)(pr >> 32);
        float v  = __uint_as_float((u32)pr);
        u64 vv = pk2(v, v);
        const ulonglong2* bp = (const ulonglong2*)(g_basis + (size_t)ci*Nn);
        #pragma unroll
        for (int j = 0; j < 8; j++) {
            ulonglong2 x = __ldg(bp + j*32 + lane);
            fma2(acc[2*j],   x.x, vv);
            fma2(acc[2*j+1], x.y, vv);
        }
    }

    float* outp = out_approx + (size_t)rr*1024;
    #pragma unroll
    for (int j = 0; j < 8; j++) {
        float4 o;
        upk2(acc[2*j],   o.x, o.y);
        upk2(acc[2*j+1], o.z, o.w);
        __stcs((float4*)outp + j*32 + lane, o);
    }

    u32 prefix = warp_kth_bits<16>(acc, BUDGET, sm_cand[warp], lane);

    float* mout = out_mask + ((size_t)bh*Nn + n)*Nn;
    #pragma unroll
    for (int j = 0; j < 8; j++) {
        unsigned u0 = (unsigned)(acc[2*j]);
        unsigned u1 = (unsigned)(acc[2*j] >> 32);
        unsigned u2 = (unsigned)(acc[2*j+1]);
        unsigned u3 = (unsigned)(acc[2*j+1] >> 32);
        float4 mo;
        mo.x = (u0 >= prefix) ? 1.0f : 0.0f;
        mo.y = (u1 >= prefix) ? 1.0f : 0.0f;
        mo.z = (u2 >= prefix) ? 1.0f : 0.0f;
        mo.w = (u3 >= prefix) ? 1.0f : 0.0f;
        __stcs((float4*)mout + j*32 + lane, mo);
    }

    if (n == 1) {
        float* cout = out_mask + (size_t)bh*Nn*Nn;
        float4 one4 = {1.0f, 1.0f, 1.0f, 1.0f};
        #pragma unroll
        for (int j = 0; j < 8; j++)
            __stcs((float4*)cout + j*32 + lane, one4);
    }
}

// ---------------- launch (k_main is 4th launch -> gets the ncu slot) ----------------
extern "C" void kernel_launch(void* const* d_in, const int* in_sizes, int n_in,
                              void* d_out, int out_size) {
    const float* q  = (const float*)d_in[0];
    const float* k  = (const float*)d_in[1];
    const float* wq = (const float*)d_in[2];
    const float* bq = (const float*)d_in[3];
    const float* wk = (const float*)d_in[4];
    const float* bk = (const float*)d_in[5];
    const float* pn = (const float*)d_in[6];
    const float* pb = (const float*)d_in[7];

    float* out        = (float*)d_out;
    float* out_coef   = out;
    float* out_approx = out + (size_t)ROWS_TOT*RNn;
    float* out_mask   = out_approx + (size_t)ROWS_TOT*Nn;

    k_prep<<<2048, 256>>>(q, k, wq, bq, wk, bk, pb);
    k_kp2_part<<<dim3(BHn, 8, 2), 256>>>(pn);
    k_kp2_red<<<1536, 256>>>();
    k_main<<<ROWS_TOT/4, 128>>>(out_coef, out_approx, out_mask);
}

// round 14
// speedup vs baseline: 2.6230x; 1.2447x over previous
#include <cuda_runtime.h>
#include <math.h>
#include <stdint.h>

#define BHn   96
#define Nn    1024
#define Cc    64
#define RCc   32
#define RNn   128
#define NM1   1023
#define ROWS_TOT (BHn*NM1)   /* 98208 */
#define KTOP  16
#define BUDGET 256

typedef unsigned long long u64;
typedef unsigned u32;

// ---------------- scratch ----------------
__device__ __align__(16) float g_qp[BHn*Nn*RCc];
__device__ __align__(16) float g_kp[BHn*Nn*RCc];
__device__ __align__(16) float g_kp2p[8*BHn*RCc*RNn];
__device__ __align__(16) float g_kp2[BHn*RCc*RNn];
__device__ __align__(16) float g_basis[RNn*Nn];

// packed f32x2 helpers (bit-identical to scalar fma per component)
__device__ __forceinline__ void fma2(u64 &d, u64 a, u64 b) {
    asm("fma.rn.f32x2 %0, %1, %2, %0;" : "+l"(d) : "l"(a), "l"(b));
}
__device__ __forceinline__ u64 pk2(float x, float y) {
    u64 r; asm("mov.b64 %0, {%1, %2};" : "=l"(r) : "f"(x), "f"(y)); return r;
}
__device__ __forceinline__ void upk2(u64 v, float &x, float &y) {
    asm("mov.b64 {%0, %1}, %2;" : "=f"(x), "=f"(y) : "l"(v));
}

// ---------------- exact warp k-th largest over NV positive floats/lane ----------------
// Binary bit-descent with float-pipe counting; returns exact bit pattern of the
// k-th largest value (= max t with count_ge(t) >= k), counting multiplicity.
template<int NV>
__device__ __forceinline__ u32 warp_kth_float(const float* v, int k, u32* sb, int lane) {
    const unsigned FULL = 0xffffffffu;
    float mx = v[0], mn = v[0];
    #pragma unroll
    for (int i = 1; i < NV; i++) { mx = fmaxf(mx, v[i]); mn = fminf(mn, v[i]); }
    #pragma unroll
    for (int off = 16; off; off >>= 1) {
        mx = fmaxf(mx, __shfl_xor_sync(FULL, mx, off));
        mn = fminf(mn, __shfl_xor_sync(FULL, mn, off));
    }
    u32 Mb = __float_as_uint(mx), mb = __float_as_uint(mn);
    if (Mb == mb) return Mb;
    int hb = 31 - __clz(Mb ^ mb);          // <= 30 for positive floats
    u32 thr = Mb & ~((2u << hb) - 1u);     // common prefix, low bits zero
    float C_lo = (float)(NV*32);           // count_ge(thr)  (all values)
    float C_up = 0.0f;                     // count_ge(window upper bound)
    const float kf = (float)k;
    int b = hb;
    #pragma unroll 1
    for (; b >= 0; b--) {
        float tf = __uint_as_float(thr | (1u << b));
        float c0 = 0.f, c1 = 0.f, c2 = 0.f, c3 = 0.f;
        #pragma unroll
        for (int i = 0; i < NV/4; i++) {
            if (v[4*i+0] >= tf) c0 += 1.0f;
            if (v[4*i+1] >= tf) c1 += 1.0f;
            if (v[4*i+2] >= tf) c2 += 1.0f;
            if (v[4*i+3] >= tf) c3 += 1.0f;
        }
        float cf = (c0 + c1) + (c2 + c3);
        #pragma unroll
        for (int off = 16; off; off >>= 1) cf += __shfl_xor_sync(FULL, cf, off);
        if (cf >= kf) { thr |= (1u << b); C_lo = cf; }
        else           C_up = cf;
        if (C_lo - C_up <= 32.0f) { b--; break; }
    }
    if (b >= 0) {
        // candidates: values in [thr, thr + 2^(b+1)) -- share prefix bits above b
        int kk = k - (int)C_up;            // rank of target within window
        u32 cmp = thr >> (b+1);
        unsigned ltm = (1u << lane) - 1u;
        int base = 0;
        #pragma unroll
        for (int i = 0; i < NV; i++) {
            u32 u = __float_as_uint(v[i]);
            bool f = (u >> (b+1)) == cmp;
            unsigned bal = __ballot_sync(FULL, f);
            if (f) sb[base + __popc(bal & ltm)] = u;
            base += __popc(bal);
        }
        __syncwarp();
        bool valid = lane < base;
        u32 cand = sb[lane];
        #pragma unroll 1
        for (int bb = b; bb >= 0; bb--) {
            u32 t2 = thr | (1u << bb);
            int cgt = __popc(__ballot_sync(FULL, valid && cand >= t2));
            if (cgt >= kk) thr = t2;
        }
        __syncwarp();
    }
    return thr;
}

// ---------------- fused prep: basis threshold + q projection + k projection ----------------
__global__ __launch_bounds__(256) void k_prep(const float* __restrict__ q,
                                              const float* __restrict__ kin,
                                              const float* __restrict__ wq,
                                              const float* __restrict__ bq,
                                              const float* __restrict__ wk,
                                              const float* __restrict__ bk,
                                              const float* __restrict__ pb) {
    int bid = blockIdx.x;
    if (bid < 512) {
        int i = bid*256 + threadIdx.x;
        if (i < RNn*Nn) {
            int j = i >> 7, c = i & 127;
            float v = fabsf(pb[i]);
            g_basis[(size_t)c*Nn + j] = (v > 0.02f) ? v : 0.0f;
        }
        return;
    }
    const float* x;
    const float* w;
    const float* b;
    float* out;
    int pbid;
    if (bid < 1280) { x = q;   w = wq; b = bq; out = g_qp; pbid = bid - 512; }
    else            { x = kin; w = wk; b = bk; out = g_kp; pbid = bid - 1280; }

    int warp = threadIdx.x >> 5, lane = threadIdx.x & 31;
    int row0 = (pbid*8 + warp)*16;
    float wr[64];
    #pragma unroll
    for (int c4 = 0; c4 < 16; c4++) {
        float4 t = *(const float4*)(w + lane*64 + c4*4);
        wr[c4*4+0]=t.x; wr[c4*4+1]=t.y; wr[c4*4+2]=t.z; wr[c4*4+3]=t.w;
    }
    float bias = b[lane];
    for (int r = 0; r < 16; r++) {
        int row = row0 + r;
        float qlo = x[(size_t)row*64 + lane];
        float qhi = x[(size_t)row*64 + 32 + lane];
        float acc = 0.0f;
        #pragma unroll
        for (int c = 0; c < 32; c++) acc = fmaf(__shfl_sync(0xffffffffu, qlo, c), wr[c],    acc);
        #pragma unroll
        for (int c = 0; c < 32; c++) acc = fmaf(__shfl_sync(0xffffffffu, qhi, c), wr[32+c], acc);
        out[(size_t)row*32 + lane] = acc + bias;
    }
}

// ---------------- kp2 partial ----------------
__global__ __launch_bounds__(256) void k_kp2_part(const float* __restrict__ proj_n) {
    __shared__ float kp_s[128*32];
    __shared__ float pj_s[128*64];
    int bh = blockIdx.x, ch = blockIdx.y, half = blockIdx.z;
    int n0 = ch*128, rnb = half*64, tid = threadIdx.x;
    const float4* src = (const float4*)(g_kp + ((size_t)bh*Nn + n0)*32);
    for (int i = tid; i < 1024; i += 256) ((float4*)kp_s)[i] = src[i];
    for (int i = tid; i < 2048; i += 256) {
        int r = i >> 4, c4 = i & 15;
        ((float4*)pj_s)[i] = *((const float4*)(proj_n + (size_t)(n0+r)*128 + rnb) + c4);
    }
    __syncthreads();
    int rc0 = (tid & 7)*4;
    int rn0 = (tid >> 3)*2;
    float a00=0,a01=0,a10=0,a11=0,a20=0,a21=0,a30=0,a31=0;
    #pragma unroll 4
    for (int n = 0; n < 128; n++) {
        float4 a = *(const float4*)(kp_s + n*32 + rc0);
        float2 p = *(const float2*)(pj_s + n*64 + rn0);
        a00 = fmaf(a.x, p.x, a00); a01 = fmaf(a.x, p.y, a01);
        a10 = fmaf(a.y, p.x, a10); a11 = fmaf(a.y, p.y, a11);
        a20 = fmaf(a.z, p.x, a20); a21 = fmaf(a.z, p.y, a21);
        a30 = fmaf(a.w, p.x, a30); a31 = fmaf(a.w, p.y, a31);
    }
    float* outp = g_kp2p + ((size_t)ch*BHn + bh)*4096 + rnb + rn0;
    *(float2*)(outp + (rc0+0)*128) = make_float2(a00, a01);
    *(float2*)(outp + (rc0+1)*128) = make_float2(a10, a11);
    *(float2*)(outp + (rc0+2)*128) = make_float2(a20, a21);
    *(float2*)(outp + (rc0+3)*128) = make_float2(a30, a31);
}

__global__ void k_kp2_red() {
    int i = blockIdx.x*256 + threadIdx.x;
    if (i < BHn*RCc*RNn) {
        float s = 0.0f;
        #pragma unroll
        for (int ch = 0; ch < 8; ch++) s += g_kp2p[(size_t)ch*BHn*4096 + i];
        g_kp2[i] = s;
    }
}

// ---------------- fused main: cheap+softmax+topk16+SpMM+top256+cls ----------------
__global__ __launch_bounds__(128) void k_main(float* __restrict__ out_coef,
                                              float* __restrict__ out_approx,
                                              float* __restrict__ out_mask) {
    __shared__ u64 sm_pair[4][16];
    __shared__ u32 sm_cand[4][32];
    int warp = threadIdx.x >> 5, lane = threadIdx.x & 31;
    const unsigned FULL = 0xffffffffu;
    int rr = blockIdx.x*4 + warp;
    int bh = rr / NM1;
    int n  = rr - bh*NM1 + 1;

    // ---- cheap attn (arithmetic unchanged) ----
    float qv = g_qp[((size_t)bh*Nn + n)*32 + lane];
    const float4* kb = (const float4*)(g_kp2 + (size_t)bh*4096);
    float4 accq = {0.f,0.f,0.f,0.f};
    #pragma unroll
    for (int rc = 0; rc < 32; rc++) {
        float a = __shfl_sync(FULL, qv, rc);
        float4 kv = __ldg(kb + rc*32 + lane);
        accq.x = fmaf(a, kv.x, accq.x);
        accq.y = fmaf(a, kv.y, accq.y);
        accq.z = fmaf(a, kv.z, accq.z);
        accq.w = fmaf(a, kv.w, accq.w);
    }
    const float scale = 0.28867513459481287f;
    float l[4] = {accq.x*scale, accq.y*scale, accq.z*scale, accq.w*scale};
    float m = fmaxf(fmaxf(l[0], l[1]), fmaxf(l[2], l[3]));
    #pragma unroll
    for (int off = 16; off; off >>= 1) m = fmaxf(m, __shfl_xor_sync(FULL, m, off));
    float e[4], s = 0.0f;
    #pragma unroll
    for (int j = 0; j < 4; j++) { e[j] = expf(l[j] - m); s += e[j]; }
    #pragma unroll
    for (int off = 16; off; off >>= 1) s += __shfl_xor_sync(FULL, s, off);
    float c[4];
    #pragma unroll
    for (int j = 0; j < 4; j++) c[j] = e[j] / s;

    // ---- topk16 via exact float bit-descent ----
    u32 T = warp_kth_float<4>(c, KTOP, sm_cand[warp], lane);
    float Tf = __uint_as_float(T);

    bool gt[4], eq[4];
    #pragma unroll
    for (int j = 0; j < 4; j++) { gt[j] = c[j] > Tf; eq[j] = c[j] == Tf; }
    unsigned balg0 = __ballot_sync(FULL, gt[0]), balg1 = __ballot_sync(FULL, gt[1]);
    unsigned balg2 = __ballot_sync(FULL, gt[2]), balg3 = __ballot_sync(FULL, gt[3]);
    unsigned bale0 = __ballot_sync(FULL, eq[0]), bale1 = __ballot_sync(FULL, eq[1]);
    unsigned bale2 = __ballot_sync(FULL, eq[2]), bale3 = __ballot_sync(FULL, eq[3]);
    int mgt = __popc(balg0) + __popc(balg1) + __popc(balg2) + __popc(balg3);
    int need = KTOP - mgt;
    unsigned ltm = (1u << lane) - 1u;
    int eq_before = __popc(bale0 & ltm) + __popc(bale1 & ltm) + __popc(bale2 & ltm) + __popc(bale3 & ltm);
    bool sel[4];
    int eqrun = eq_before;
    #pragma unroll
    for (int j = 0; j < 4; j++) {
        sel[j] = gt[j] || (eq[j] && (eqrun < need));
        if (eq[j]) eqrun++;
    }

    // coef row
    {
        float4 o;
        o.x = sel[0] ? c[0] : 0.0f;
        o.y = sel[1] ? c[1] : 0.0f;
        o.z = sel[2] ? c[2] : 0.0f;
        o.w = sel[3] ? c[3] : 0.0f;
        *(float4*)(out_coef + (size_t)rr*128 + lane*4) = o;
    }

    // pack 16 selected (idx,val) pairs, ascending idx
    unsigned bs0 = __ballot_sync(FULL, sel[0]), bs1 = __ballot_sync(FULL, sel[1]);
    unsigned bs2 = __ballot_sync(FULL, sel[2]), bs3 = __ballot_sync(FULL, sel[3]);
    int run = __popc(bs0 & ltm) + __popc(bs1 & ltm) + __popc(bs2 & ltm) + __popc(bs3 & ltm);
    #pragma unroll
    for (int j = 0; j < 4; j++) {
        if (sel[j]) { sm_pair[warp][run] = ((u64)(unsigned)(lane*4 + j) << 32) | (u64)__float_as_uint(c[j]); run++; }
    }
    __syncwarp();

    // ---- sparse SpMM: ascending idx, packed f32x2 (order identical to reference) ----
    u64 acc[16];
    #pragma unroll
    for (int j = 0; j < 16; j++) acc[j] = 0ULL;
    #pragma unroll 4
    for (int t = 0; t < 16; t++) {
        u64 pr = sm_pair[warp][t];
        int   ci = (int)(pr >> 32);
        float v  = __uint_as_float((u32)pr);
        u64 vv = pk2(v, v);
        const ulonglong2* bp = (const ulonglong2*)(g_basis + (size_t)ci*Nn);
        #pragma unroll
        for (int j = 0; j < 8; j++) {
            ulonglong2 x = __ldg(bp + j*32 + lane);
            fma2(acc[2*j],   x.x, vv);
            fma2(acc[2*j+1], x.y, vv);
        }
    }

    // approx_attn (streaming)
    float* outp = out_approx + (size_t)rr*1024;
    #pragma unroll
    for (int j = 0; j < 8; j++) {
        float4 o;
        upk2(acc[2*j],   o.x, o.y);
        upk2(acc[2*j+1], o.z, o.w);
        __stcs((float4*)outp + j*32 + lane, o);
    }

    // ---- exact top-256 threshold via float bit-descent ----
    float v32[32];
    #pragma unroll
    for (int j = 0; j < 8; j++) {
        upk2(acc[2*j],   v32[4*j+0], v32[4*j+1]);
        upk2(acc[2*j+1], v32[4*j+2], v32[4*j+3]);
    }
    u32 prefix = warp_kth_float<32>(v32, BUDGET, sm_cand[warp], lane);
    float pf = __uint_as_float(prefix);

    // ---- mask row: v >= threshold (float compare == bit compare for positives) ----
    float* mout = out_mask + ((size_t)bh*Nn + n)*Nn;
    #pragma unroll
    for (int j = 0; j < 8; j++) {
        float4 mo;
        mo.x = (v32[4*j+0] >= pf) ? 1.0f : 0.0f;
        mo.y = (v32[4*j+1] >= pf) ? 1.0f : 0.0f;
        mo.z = (v32[4*j+2] >= pf) ? 1.0f : 0.0f;
        mo.w = (v32[4*j+3] >= pf) ? 1.0f : 0.0f;
        __stcs((float4*)mout + j*32 + lane, mo);
    }

    // cls row of this bh (exactly one warp per bh has n==1)
    if (n == 1) {
        float* cout = out_mask + (size_t)bh*Nn*Nn;
        float4 one4 = {1.0f, 1.0f, 1.0f, 1.0f};
        #pragma unroll
        for (int j = 0; j < 8; j++)
            __stcs((float4*)cout + j*32 + lane, one4);
    }
}

// ---------------- launch (k_main is 4th launch -> gets the ncu slot) ----------------
extern "C" void kernel_launch(void* const* d_in, const int* in_sizes, int n_in,
                              void* d_out, int out_size) {
    const float* q  = (const float*)d_in[0];
    const float* k  = (const float*)d_in[1];
    const float* wq = (const float*)d_in[2];
    const float* bq = (const float*)d_in[3];
    const float* wk = (const float*)d_in[4];
    const float* bk = (const float*)d_in[5];
    const float* pn = (const float*)d_in[6];
    const float* pb = (const float*)d_in[7];

    float* out        = (float*)d_out;
    float* out_coef   = out;
    float* out_approx = out + (size_t)ROWS_TOT*RNn;
    float* out_mask   = out_approx + (size_t)ROWS_TOT*Nn;

    k_prep<<<2048, 256>>>(q, k, wq, bq, wk, bk, pb);
    k_kp2_part<<<dim3(BHn, 8, 2), 256>>>(pn);
    k_kp2_red<<<1536, 256>>>();
    k_main<<<ROWS_TOT/4, 128>>>(out_coef, out_approx, out_mask);
}

// round 16
// speedup vs baseline: 2.7324x; 1.0417x over previous
#include <cuda_runtime.h>
#include <math.h>
#include <stdint.h>

#define BHn   96
#define Nn    1024
#define Cc    64
#define RCc   32
#define RNn   128
#define NM1   1023
#define ROWS_TOT (BHn*NM1)   /* 98208 */
#define KTOP  16
#define BUDGET 256

typedef unsigned long long u64;
typedef unsigned u32;

// ---------------- scratch ----------------
__device__ __align__(16) float g_qp[BHn*Nn*RCc];
__device__ __align__(16) float g_kp[BHn*Nn*RCc];
__device__ __align__(16) float g_kp2p[8*BHn*RCc*RNn];
__device__ __align__(16) float g_kp2[BHn*RCc*RNn];
__device__ __align__(16) float g_basis[RNn*Nn];

// packed f32x2 helpers (bit-identical to scalar fma per component)
__device__ __forceinline__ void fma2(u64 &d, u64 a, u64 b) {
    asm("fma.rn.f32x2 %0, %1, %2, %0;" : "+l"(d) : "l"(a), "l"(b));
}
__device__ __forceinline__ u64 pk2(float x, float y) {
    u64 r; asm("mov.b64 %0, {%1, %2};" : "=l"(r) : "f"(x), "f"(y)); return r;
}
__device__ __forceinline__ void upk2(u64 v, float &x, float &y) {
    asm("mov.b64 {%0, %1}, %2;" : "=f"(x), "=f"(y) : "l"(v));
}

// ---------------- exact warp k-th largest over NV positive floats/lane ----------------
// Binary bit-descent with float-pipe counting; candidates <=32 finished by a
// 32-lane bitonic sort (exact rank with multiplicity). Returns kth-largest bits.
template<int NV>
__device__ __forceinline__ u32 warp_kth_float(const float* v, int k, u32* sb, int lane) {
    const unsigned FULL = 0xffffffffu;
    float mx = v[0], mn = v[0];
    #pragma unroll
    for (int i = 1; i < NV; i++) { mx = fmaxf(mx, v[i]); mn = fminf(mn, v[i]); }
    #pragma unroll
    for (int off = 16; off; off >>= 1) {
        mx = fmaxf(mx, __shfl_xor_sync(FULL, mx, off));
        mn = fminf(mn, __shfl_xor_sync(FULL, mn, off));
    }
    u32 Mb = __float_as_uint(mx), mb = __float_as_uint(mn);
    if (Mb == mb) return Mb;
    int hb = 31 - __clz(Mb ^ mb);          // <= 30 for positive floats
    u32 thr = Mb & ~((2u << hb) - 1u);     // common prefix, low bits zero
    float C_lo = (float)(NV*32);           // count_ge(thr)  (all values)
    float C_up = 0.0f;                     // count_ge(window upper bound)
    const float kf = (float)k;
    int b = hb;
    #pragma unroll 1
    for (; b >= 0; b--) {
        float tf = __uint_as_float(thr | (1u << b));
        float c0 = 0.f, c1 = 0.f, c2 = 0.f, c3 = 0.f;
        #pragma unroll
        for (int i = 0; i < NV/4; i++) {
            if (v[4*i+0] >= tf) c0 += 1.0f;
            if (v[4*i+1] >= tf) c1 += 1.0f;
            if (v[4*i+2] >= tf) c2 += 1.0f;
            if (v[4*i+3] >= tf) c3 += 1.0f;
        }
        float cf = (c0 + c1) + (c2 + c3);
        #pragma unroll
        for (int off = 16; off; off >>= 1) cf += __shfl_xor_sync(FULL, cf, off);
        if (cf >= kf) { thr |= (1u << b); C_lo = cf; }
        else           C_up = cf;
        if (C_lo - C_up <= 32.0f) { b--; break; }
    }
    if (b >= 0) {
        // candidates: values sharing prefix bits above b  (count = C_lo - C_up <= 32)
        int kk = k - (int)C_up;            // rank of target within window (1..32)
        u32 cmp = thr >> (b+1);
        unsigned ltm = (1u << lane) - 1u;
        int base = 0;
        #pragma unroll
        for (int i = 0; i < NV; i++) {
            u32 u = __float_as_uint(v[i]);
            bool f = (u >> (b+1)) == cmp;
            unsigned bal = __ballot_sync(FULL, f);
            if (f) sb[base + __popc(bal & ltm)] = u;
            base += __popc(bal);
        }
        __syncwarp();
        float cand = (lane < base) ? __uint_as_float(sb[lane]) : 0.0f;
        // 32-lane bitonic sort, descending (positive floats: float order == bit order)
        #pragma unroll
        for (int kq = 2; kq <= 32; kq <<= 1) {
            #pragma unroll
            for (int j = kq >> 1; j > 0; j >>= 1) {
                float other = __shfl_xor_sync(FULL, cand, j);
                bool smaller = ((lane & j) == 0);
                bool dir = ((lane & kq) == 0);
                cand = (dir == smaller) ? fmaxf(cand, other) : fminf(cand, other);
            }
        }
        thr = __shfl_sync(FULL, __float_as_uint(cand), kk - 1);
        __syncwarp();
    }
    return thr;
}

// ---------------- fused prep: basis threshold + q projection + k projection ----------------
__global__ __launch_bounds__(256) void k_prep(const float* __restrict__ q,
                                              const float* __restrict__ kin,
                                              const float* __restrict__ wq,
                                              const float* __restrict__ bq,
                                              const float* __restrict__ wk,
                                              const float* __restrict__ bk,
                                              const float* __restrict__ pb) {
    int bid = blockIdx.x;
    if (bid < 512) {
        int i = bid*256 + threadIdx.x;
        if (i < RNn*Nn) {
            int j = i >> 7, c = i & 127;
            float v = fabsf(pb[i]);
            g_basis[(size_t)c*Nn + j] = (v > 0.02f) ? v : 0.0f;
        }
        return;
    }
    const float* x;
    const float* w;
    const float* b;
    float* out;
    int pbid;
    if (bid < 1280) { x = q;   w = wq; b = bq; out = g_qp; pbid = bid - 512; }
    else            { x = kin; w = wk; b = bk; out = g_kp; pbid = bid - 1280; }

    int warp = threadIdx.x >> 5, lane = threadIdx.x & 31;
    int row0 = (pbid*8 + warp)*16;
    float wr[64];
    #pragma unroll
    for (int c4 = 0; c4 < 16; c4++) {
        float4 t = *(const float4*)(w + lane*64 + c4*4);
        wr[c4*4+0]=t.x; wr[c4*4+1]=t.y; wr[c4*4+2]=t.z; wr[c4*4+3]=t.w;
    }
    float bias = b[lane];
    for (int r = 0; r < 16; r++) {
        int row = row0 + r;
        float qlo = x[(size_t)row*64 + lane];
        float qhi = x[(size_t)row*64 + 32 + lane];
        float acc = 0.0f;
        #pragma unroll
        for (int c = 0; c < 32; c++) acc = fmaf(__shfl_sync(0xffffffffu, qlo, c), wr[c],    acc);
        #pragma unroll
        for (int c = 0; c < 32; c++) acc = fmaf(__shfl_sync(0xffffffffu, qhi, c), wr[32+c], acc);
        out[(size_t)row*32 + lane] = acc + bias;
    }
}

// ---------------- kp2 partial ----------------
__global__ __launch_bounds__(256) void k_kp2_part(const float* __restrict__ proj_n) {
    __shared__ float kp_s[128*32];
    __shared__ float pj_s[128*64];
    int bh = blockIdx.x, ch = blockIdx.y, half = blockIdx.z;
    int n0 = ch*128, rnb = half*64, tid = threadIdx.x;
    const float4* src = (const float4*)(g_kp + ((size_t)bh*Nn + n0)*32);
    for (int i = tid; i < 1024; i += 256) ((float4*)kp_s)[i] = src[i];
    for (int i = tid; i < 2048; i += 256) {
        int r = i >> 4, c4 = i & 15;
        ((float4*)pj_s)[i] = *((const float4*)(proj_n + (size_t)(n0+r)*128 + rnb) + c4);
    }
    __syncthreads();
    int rc0 = (tid & 7)*4;
    int rn0 = (tid >> 3)*2;
    float a00=0,a01=0,a10=0,a11=0,a20=0,a21=0,a30=0,a31=0;
    #pragma unroll 4
    for (int n = 0; n < 128; n++) {
        float4 a = *(const float4*)(kp_s + n*32 + rc0);
        float2 p = *(const float2*)(pj_s + n*64 + rn0);
        a00 = fmaf(a.x, p.x, a00); a01 = fmaf(a.x, p.y, a01);
        a10 = fmaf(a.y, p.x, a10); a11 = fmaf(a.y, p.y, a11);
        a20 = fmaf(a.z, p.x, a20); a21 = fmaf(a.z, p.y, a21);
        a30 = fmaf(a.w, p.x, a30); a31 = fmaf(a.w, p.y, a31);
    }
    float* outp = g_kp2p + ((size_t)ch*BHn + bh)*4096 + rnb + rn0;
    *(float2*)(outp + (rc0+0)*128) = make_float2(a00, a01);
    *(float2*)(outp + (rc0+1)*128) = make_float2(a10, a11);
    *(float2*)(outp + (rc0+2)*128) = make_float2(a20, a21);
    *(float2*)(outp + (rc0+3)*128) = make_float2(a30, a31);
}

__global__ void k_kp2_red() {
    int i = blockIdx.x*256 + threadIdx.x;
    if (i < BHn*RCc*RNn) {
        float s = 0.0f;
        #pragma unroll
        for (int ch = 0; ch < 8; ch++) s += g_kp2p[(size_t)ch*BHn*4096 + i];
        g_kp2[i] = s;
    }
}

// ---------------- fused main: cheap+softmax+topk16+SpMM+top256+cls ----------------
__global__ __launch_bounds__(128) void k_main(float* __restrict__ out_coef,
                                              float* __restrict__ out_approx,
                                              float* __restrict__ out_mask) {
    __shared__ u64 sm_pair[4][16];
    __shared__ u32 sm_cand[4][32];
    int warp = threadIdx.x >> 5, lane = threadIdx.x & 31;
    const unsigned FULL = 0xffffffffu;
    int rr = blockIdx.x*4 + warp;
    int bh = rr / NM1;
    int n  = rr - bh*NM1 + 1;

    // ---- cheap attn on packed f32x2 (bit-identical per component) ----
    float qv = g_qp[((size_t)bh*Nn + n)*32 + lane];
    const ulonglong2* kb2 = (const ulonglong2*)(g_kp2 + (size_t)bh*4096);
    u64 acc01 = 0ULL, acc23 = 0ULL;
    #pragma unroll
    for (int rc = 0; rc < 32; rc++) {
        float a = __shfl_sync(FULL, qv, rc);
        u64 aa = pk2(a, a);
        ulonglong2 kv = __ldg(kb2 + rc*32 + lane);
        fma2(acc01, kv.x, aa);
        fma2(acc23, kv.y, aa);
    }
    float ax, ay, az, aw;
    upk2(acc01, ax, ay);
    upk2(acc23, az, aw);
    const float scale = 0.28867513459481287f;
    float l[4] = {ax*scale, ay*scale, az*scale, aw*scale};
    float m = fmaxf(fmaxf(l[0], l[1]), fmaxf(l[2], l[3]));
    #pragma unroll
    for (int off = 16; off; off >>= 1) m = fmaxf(m, __shfl_xor_sync(FULL, m, off));
    float e[4], s = 0.0f;
    #pragma unroll
    for (int j = 0; j < 4; j++) { e[j] = expf(l[j] - m); s += e[j]; }
    #pragma unroll
    for (int off = 16; off; off >>= 1) s += __shfl_xor_sync(FULL, s, off);
    float c[4];
    #pragma unroll
    for (int j = 0; j < 4; j++) c[j] = e[j] / s;

    // ---- topk16 via exact float bit-descent ----
    u32 T = warp_kth_float<4>(c, KTOP, sm_cand[warp], lane);
    float Tf = __uint_as_float(T);

    bool gt[4], eq[4];
    #pragma unroll
    for (int j = 0; j < 4; j++) { gt[j] = c[j] > Tf; eq[j] = c[j] == Tf; }
    unsigned balg0 = __ballot_sync(FULL, gt[0]), balg1 = __ballot_sync(FULL, gt[1]);
    unsigned balg2 = __ballot_sync(FULL, gt[2]), balg3 = __ballot_sync(FULL, gt[3]);
    unsigned bale0 = __ballot_sync(FULL, eq[0]), bale1 = __ballot_sync(FULL, eq[1]);
    unsigned bale2 = __ballot_sync(FULL, eq[2]), bale3 = __ballot_sync(FULL, eq[3]);
    int mgt = __popc(balg0) + __popc(balg1) + __popc(balg2) + __popc(balg3);
    int need = KTOP - mgt;
    unsigned ltm = (1u << lane) - 1u;
    int eq_before = __popc(bale0 & ltm) + __popc(bale1 & ltm) + __popc(bale2 & ltm) + __popc(bale3 & ltm);
    bool sel[4];
    int eqrun = eq_before;
    #pragma unroll
    for (int j = 0; j < 4; j++) {
        sel[j] = gt[j] || (eq[j] && (eqrun < need));
        if (eq[j]) eqrun++;
    }

    // coef row
    {
        float4 o;
        o.x = sel[0] ? c[0] : 0.0f;
        o.y = sel[1] ? c[1] : 0.0f;
        o.z = sel[2] ? c[2] : 0.0f;
        o.w = sel[3] ? c[3] : 0.0f;
        *(float4*)(out_coef + (size_t)rr*128 + lane*4) = o;
    }

    // pack 16 selected (idx,val) pairs, ascending idx
    unsigned bs0 = __ballot_sync(FULL, sel[0]), bs1 = __ballot_sync(FULL, sel[1]);
    unsigned bs2 = __ballot_sync(FULL, sel[2]), bs3 = __ballot_sync(FULL, sel[3]);
    int run = __popc(bs0 & ltm) + __popc(bs1 & ltm) + __popc(bs2 & ltm) + __popc(bs3 & ltm);
    #pragma unroll
    for (int j = 0; j < 4; j++) {
        if (sel[j]) { sm_pair[warp][run] = ((u64)(unsigned)(lane*4 + j) << 32) | (u64)__float_as_uint(c[j]); run++; }
    }
    __syncwarp();

    // ---- sparse SpMM: ascending idx, packed f32x2 (order identical to reference) ----
    u64 acc[16];
    #pragma unroll
    for (int j = 0; j < 16; j++) acc[j] = 0ULL;
    #pragma unroll 4
    for (int t = 0; t < 16; t++) {
        u64 pr = sm_pair[warp][t];
        int   ci = (int)(pr >> 32);
        float v  = __uint_as_float((u32)pr);
        u64 vv = pk2(v, v);
        const ulonglong2* bp = (const ulonglong2*)(g_basis + (size_t)ci*Nn);
        #pragma unroll
        for (int j = 0; j < 8; j++) {
            ulonglong2 x = __ldg(bp + j*32 + lane);
            fma2(acc[2*j],   x.x, vv);
            fma2(acc[2*j+1], x.y, vv);
        }
    }

    // approx_attn (streaming)
    float* outp = out_approx + (size_t)rr*1024;
    #pragma unroll
    for (int j = 0; j < 8; j++) {
        float4 o;
        upk2(acc[2*j],   o.x, o.y);
        upk2(acc[2*j+1], o.z, o.w);
        __stcs((float4*)outp + j*32 + lane, o);
    }

    // ---- exact top-256 threshold via float bit-descent ----
    float v32[32];
    #pragma unroll
    for (int j = 0; j < 8; j++) {
        upk2(acc[2*j],   v32[4*j+0], v32[4*j+1]);
        upk2(acc[2*j+1], v32[4*j+2], v32[4*j+3]);
    }
    u32 prefix = warp_kth_float<32>(v32, BUDGET, sm_cand[warp], lane);
    float pf = __uint_as_float(prefix);

    // ---- mask row: v >= threshold (float compare == bit compare for positives) ----
    float* mout = out_mask + ((size_t)bh*Nn + n)*Nn;
    #pragma unroll
    for (int j = 0; j < 8; j++) {
        float4 mo;
        mo.x = (v32[4*j+0] >= pf) ? 1.0f : 0.0f;
        mo.y = (v32[4*j+1] >= pf) ? 1.0f : 0.0f;
        mo.z = (v32[4*j+2] >= pf) ? 1.0f : 0.0f;
        mo.w = (v32[4*j+3] >= pf) ? 1.0f : 0.0f;
        __stcs((float4*)mout + j*32 + lane, mo);
    }

    // cls row of this bh (exactly one warp per bh has n==1)
    if (n == 1) {
        float* cout = out_mask + (size_t)bh*Nn*Nn;
        float4 one4 = {1.0f, 1.0f, 1.0f, 1.0f};
        #pragma unroll
        for (int j = 0; j < 8; j++)
            __stcs((float4*)cout + j*32 + lane, one4);
    }
}

// ---------------- launch (k_main is 4th launch -> gets the ncu slot) ----------------
extern "C" void kernel_launch(void* const* d_in, const int* in_sizes, int n_in,
                              void* d_out, int out_size) {
    const float* q  = (const float*)d_in[0];
    const float* k  = (const float*)d_in[1];
    const float* wq = (const float*)d_in[2];
    const float* bq = (const float*)d_in[3];
    const float* wk = (const float*)d_in[4];
    const float* bk = (const float*)d_in[5];
    const float* pn = (const float*)d_in[6];
    const float* pb = (const float*)d_in[7];

    float* out        = (float*)d_out;
    float* out_coef   = out;
    float* out_approx = out + (size_t)ROWS_TOT*RNn;
    float* out_mask   = out_approx + (size_t)ROWS_TOT*Nn;

    k_prep<<<2048, 256>>>(q, k, wq, bq, wk, bk, pb);
    k_kp2_part<<<dim3(BHn, 8, 2), 256>>>(pn);
    k_kp2_red<<<1536, 256>>>();
    k_main<<<ROWS_TOT/4, 128>>>(out_coef, out_approx, out_mask);
}